// round 1
// baseline (speedup 1.0000x reference)
#include <cuda_runtime.h>
#include <cstdint>

// ---------------------------------------------------------------------------
// MLPDecoder (NRI-style) — fp32 baseline with algebraic layer-1 factorization
//
// Shapes: B=4, A=32, T=64, D=64, S=4, E=4 (experts 1..3 active), R=992
//   MH=MO=NH=256.  Nodes N = B*T*A = 8192. Edges per (b,t): 992 (rec-major).
//
// Pipeline:
//   k1x : inputs[B,A,T,D] -> Xn[node=(b,t,a)][64]
//   k1g : gates G[e][bt*992+r] = sum_s rel_type[b,r,s,e+1]*state[b,send,t,s]
//   k2  : P,Q node GEMMs:  PQ[e*2+half][node][256] = Xn @ W1 halves (+b1 on P)
//   k3  : edge GEMM (the 100-GFLOP workhorse):
//           h1 = lrelu(P[send]+Q[rec]); h2 = lrelu(h1@W2 + b2); agg += h2*g
//         block = one (b,t) x 4 receivers (128 rows incl. 1 dummy/receiver),
//         FFMA2-packed over row pairs, agg reduced in registers.
//   k5  : output MLP (aug=[x|agg] -> 256 -> 256 -> 64), +x, write [B,A,63,D]
// ---------------------------------------------------------------------------

#define NNODE   8192
#define NEDGE   253952       // 256*992
#define NBT     256

// Scratch (static device globals; allocation-free)
__device__ float d_X  [NNODE * 64];
__device__ float d_PQ [6 * NNODE * 256];     // [e*2+half][node][256]
__device__ float d_G  [3 * NEDGE];
__device__ float d_AGG[NNODE * 256];

__device__ __forceinline__ float lrelu(float v) {
    return fmaxf(v, 0.01f * v);
}
__device__ __forceinline__ unsigned long long dup2(float w) {
    unsigned long long r;
    unsigned int u = __float_as_uint(w);
    asm("mov.b64 %0, {%1, %1};" : "=l"(r) : "r"(u));
    return r;
}
__device__ __forceinline__ void ffma2(unsigned long long& d,
                                      unsigned long long a,
                                      unsigned long long b) {
    asm("fma.rn.f32x2 %0, %1, %2, %0;" : "+l"(d) : "l"(a), "l"(b));
}
__device__ __forceinline__ float lo32(unsigned long long v) {
    return __uint_as_float((unsigned int)(v & 0xffffffffull));
}
__device__ __forceinline__ float hi32(unsigned long long v) {
    return __uint_as_float((unsigned int)(v >> 32));
}

// ------------------------- k1x: node-layout transpose ----------------------
__global__ void k1x(const float4* __restrict__ inputs4) {
    int idx = blockIdx.x * blockDim.x + threadIdx.x;       // < 131072
    if (idx >= NNODE * 16) return;
    int n = idx >> 4, q = idx & 15;
    int b = n >> 11, t = (n >> 5) & 63, a = n & 31;
    ((float4*)d_X)[idx] = inputs4[(((b * 32 + a) * 64) + t) * 16 + q];
}

// ------------------------- k1g: edge gates ---------------------------------
__global__ void k1g(const float* __restrict__ state,
                    const float4* __restrict__ rel_type4) {
    int idx = blockIdx.x * blockDim.x + threadIdx.x;       // < 253952
    if (idx >= NEDGE) return;
    int bt = idx / 992, r = idx - bt * 992;
    int b = bt >> 6, t = bt & 63;
    int rec = r / 31, j = r - rec * 31;
    int send = j + (j >= rec);
    const float4 st = *(const float4*)&state[(((b * 32 + send) * 64) + t) * 4];
    // rel_type[b][r][s][e] : 16 floats = 4 float4 (one per s)
    const float4* rt = rel_type4 + (b * 992 + r) * 4;
    float4 r0 = rt[0], r1 = rt[1], r2 = rt[2], r3 = rt[3];
    // e index in float4: .y = e1, .z = e2, .w = e3
    d_G[0 * NEDGE + idx] = st.x * r0.y + st.y * r1.y + st.z * r2.y + st.w * r3.y;
    d_G[1 * NEDGE + idx] = st.x * r0.z + st.y * r1.z + st.z * r2.z + st.w * r3.z;
    d_G[2 * NEDGE + idx] = st.x * r0.w + st.y * r1.w + st.z * r2.w + st.w * r3.w;
}

// ------------------------- k2: P/Q node GEMMs ------------------------------
// grid 256 blocks x 256 threads; each block: 32 node rows, all 6 (e,half).
__global__ __launch_bounds__(256) void k2(const float* __restrict__ w1,
                                          const float* __restrict__ b1) {
    __shared__ float xs[32][64];
    int row0 = blockIdx.x * 32;
    int tid = threadIdx.x;
    for (int i = tid; i < 32 * 64; i += 256)
        xs[i >> 6][i & 63] = d_X[row0 * 64 + i];
    __syncthreads();

    for (int chunk = 0; chunk < 6; ++chunk) {
        int e = chunk >> 1, half = chunk & 1;
        const float* W = w1 + ((size_t)((e + 1) * 128 + half * 64)) * 256;
        float acc[32];
#pragma unroll
        for (int m = 0; m < 32; ++m) acc[m] = 0.f;
#pragma unroll 4
        for (int k = 0; k < 64; ++k) {
            float w = W[k * 256 + tid];
#pragma unroll
            for (int m = 0; m < 32; ++m) acc[m] += xs[m][k] * w;
        }
        float bias = (half == 0) ? b1[(e + 1) * 256 + tid] : 0.f;
        float* dst = d_PQ + ((size_t)chunk * NNODE + row0) * 256 + tid;
#pragma unroll
        for (int m = 0; m < 32; ++m) dst[m * 256] = acc[m] + bias;
    }
}

// ------------------------- k3: edge GEMM + gated aggregation ---------------
// grid 2048 blocks (bt*8 + receiver-quad), 256 threads.
// smem: h1T[256][130] (transposed, padded) + g_s[128]
#define K3_SMEM (256 * 130 * 4 + 128 * 4)

__global__ __launch_bounds__(256, 1) void k3(const float* __restrict__ w2,
                                             const float* __restrict__ b2) {
    extern __shared__ float smem[];
    float* h1T = smem;                 // [k][m], stride 130
    float* g_s = smem + 256 * 130;     // [128]

    int tid = threadIdx.x;
    int bt = blockIdx.x >> 3;
    int a0 = (blockIdx.x & 7) << 2;
    int cg = tid & 63, rg = tid >> 6;
    int c0 = cg * 4;

    float aggv0 = 0.f, aggv1 = 0.f, aggv2 = 0.f, aggv3 = 0.f;

    for (int e = 0; e < 3; ++e) {
        // ---- build h1T (thread tid = feature k) ----
        {
            const float* Pb = d_PQ + ((size_t)(e * 2) * NNODE + bt * 32) * 256 + tid;
            const float* Qb = d_PQ + ((size_t)(e * 2 + 1) * NNODE + bt * 32) * 256 + tid;
            float* hrow = h1T + tid * 130;
#pragma unroll
            for (int grp = 0; grp < 4; ++grp) {
                int rec = a0 + grp;
                float q = Qb[rec * 256];
#pragma unroll 31
                for (int j = 0; j < 31; ++j) {
                    int send = j + (j >= rec);
                    float v = Pb[send * 256] + q;
                    hrow[grp * 32 + j] = lrelu(v);
                }
                hrow[grp * 32 + 31] = 0.f;   // dummy row
            }
        }
        if (tid < 128) {
            int grp = tid >> 5, j = tid & 31;
            g_s[tid] = (j < 31)
                ? d_G[e * NEDGE + bt * 992 + (a0 + grp) * 31 + j] : 0.f;
        }
        __syncthreads();

        // ---- GEMM: 128 rows x 256 cols x 256 K, FFMA2 over row pairs ----
        unsigned long long acc2[16][4];
#pragma unroll
        for (int p = 0; p < 16; ++p)
#pragma unroll
            for (int c = 0; c < 4; ++c) acc2[p][c] = 0ull;

        const float* W = w2 + (size_t)(e + 1) * 65536 + c0;   // row stride 256
        const float* hbase = h1T + rg * 32;

        float4 wv = *(const float4*)W;
#pragma unroll 2
        for (int k = 0; k < 256; ++k) {
            int kn = (k < 255) ? k + 1 : 255;
            float4 wnext = *(const float4*)(W + kn * 256);
            unsigned long long wd0 = dup2(wv.x), wd1 = dup2(wv.y);
            unsigned long long wd2 = dup2(wv.z), wd3 = dup2(wv.w);
            const unsigned long long* hp =
                (const unsigned long long*)(hbase + k * 130);
#pragma unroll
            for (int p = 0; p < 16; ++p) {
                unsigned long long h2 = hp[p];
                ffma2(acc2[p][0], h2, wd0);
                ffma2(acc2[p][1], h2, wd1);
                ffma2(acc2[p][2], h2, wd2);
                ffma2(acc2[p][3], h2, wd3);
            }
            wv = wnext;
        }

        // ---- epilogue: lrelu(+b2), gate, reduce rows ----
        float4 b2v = *(const float4*)(b2 + (e + 1) * 256 + c0);
        float bc0 = b2v.x, bc1 = b2v.y, bc2 = b2v.z, bc3 = b2v.w;
#pragma unroll
        for (int p = 0; p < 16; ++p) {
            float glo = g_s[rg * 32 + 2 * p];
            float ghi = g_s[rg * 32 + 2 * p + 1];
            aggv0 += lrelu(lo32(acc2[p][0]) + bc0) * glo
                   + lrelu(hi32(acc2[p][0]) + bc0) * ghi;
            aggv1 += lrelu(lo32(acc2[p][1]) + bc1) * glo
                   + lrelu(hi32(acc2[p][1]) + bc1) * ghi;
            aggv2 += lrelu(lo32(acc2[p][2]) + bc2) * glo
                   + lrelu(hi32(acc2[p][2]) + bc2) * ghi;
            aggv3 += lrelu(lo32(acc2[p][3]) + bc3) * glo
                   + lrelu(hi32(acc2[p][3]) + bc3) * ghi;
        }
        __syncthreads();   // before next expert overwrites h1T / g_s
    }

    int node = bt * 32 + a0 + rg;
    float4 o; o.x = aggv0; o.y = aggv1; o.z = aggv2; o.w = aggv3;
    *(float4*)(d_AGG + (size_t)node * 256 + c0) = o;
}

// ------------------------- k5: output MLP + residual + write ---------------
// grid 512 blocks x 256 threads; 16 node rows per block.
__global__ __launch_bounds__(256) void k5(const float* __restrict__ fw1,
                                          const float* __restrict__ fb1,
                                          const float* __restrict__ fw2,
                                          const float* __restrict__ fb2,
                                          const float* __restrict__ fw3,
                                          const float* __restrict__ fb3,
                                          float* __restrict__ out) {
    __shared__ float aug[16][320];     // also reused as h2 buffer
    __shared__ float hbuf[16][256];
    int row0 = blockIdx.x * 16;
    int tid = threadIdx.x;

    for (int i = tid; i < 16 * 64; i += 256)
        aug[i >> 6][i & 63] = d_X[row0 * 64 + i];
    for (int i = tid; i < 16 * 256; i += 256)
        aug[i >> 8][64 + (i & 255)] = d_AGG[(size_t)row0 * 256 + i];
    __syncthreads();

    // layer 1: 320 -> 256
    {
        float acc[16];
#pragma unroll
        for (int m = 0; m < 16; ++m) acc[m] = 0.f;
#pragma unroll 4
        for (int k = 0; k < 320; ++k) {
            float w = fw1[k * 256 + tid];
#pragma unroll
            for (int m = 0; m < 16; ++m) acc[m] += aug[m][k] * w;
        }
        float b = fb1[tid];
#pragma unroll
        for (int m = 0; m < 16; ++m) hbuf[m][tid] = lrelu(acc[m] + b);
    }
    __syncthreads();

    // layer 2: 256 -> 256 (output into aug buffer)
    {
        float acc[16];
#pragma unroll
        for (int m = 0; m < 16; ++m) acc[m] = 0.f;
#pragma unroll 4
        for (int k = 0; k < 256; ++k) {
            float w = fw2[k * 256 + tid];
#pragma unroll
            for (int m = 0; m < 16; ++m) acc[m] += hbuf[m][k] * w;
        }
        float b = fb2[tid];
#pragma unroll
        for (int m = 0; m < 16; ++m) aug[m][tid] = lrelu(acc[m] + b);
    }
    __syncthreads();

    // layer 3: 256 -> 64, residual, write out (skip t = 63)
    {
        int c = tid & 63, sub = tid >> 6;       // 4 subs x 4 rows
        float acc3[4] = {0.f, 0.f, 0.f, 0.f};
#pragma unroll 4
        for (int k = 0; k < 256; ++k) {
            float w = fw3[k * 64 + c];
#pragma unroll
            for (int mm = 0; mm < 4; ++mm) acc3[mm] += aug[sub * 4 + mm][k] * w;
        }
        float b = fb3[c];
#pragma unroll
        for (int mm = 0; mm < 4; ++mm) {
            int m = sub * 4 + mm;
            int n = row0 + m;
            int bb = n >> 11, t = (n >> 5) & 63, a = n & 31;
            if (t < 63) {
                out[(((bb * 32 + a) * 63) + t) * 64 + c] =
                    d_X[n * 64 + c] + acc3[mm] + b;
            }
        }
    }
}

// ---------------------------------------------------------------------------
extern "C" void kernel_launch(void* const* d_in, const int* in_sizes, int n_in,
                              void* d_out, int out_size) {
    (void)in_sizes; (void)n_in; (void)out_size;
    const float* inputs    = (const float*)d_in[0];
    const float* state     = (const float*)d_in[1];
    const float* rel_type  = (const float*)d_in[2];
    // d_in[3] rel_rec, d_in[4] rel_send: structure derived analytically
    const float* msg_fc1_w = (const float*)d_in[5];
    const float* msg_fc1_b = (const float*)d_in[6];
    const float* msg_fc2_w = (const float*)d_in[7];
    const float* msg_fc2_b = (const float*)d_in[8];
    const float* out_fc1_w = (const float*)d_in[9];
    const float* out_fc1_b = (const float*)d_in[10];
    const float* out_fc2_w = (const float*)d_in[11];
    const float* out_fc2_b = (const float*)d_in[12];
    const float* out_fc3_w = (const float*)d_in[13];
    const float* out_fc3_b = (const float*)d_in[14];
    float* out = (float*)d_out;

    k1x<<<(NNODE * 16 + 255) / 256, 256>>>((const float4*)inputs);
    k1g<<<(NEDGE + 255) / 256, 256>>>(state, (const float4*)rel_type);
    k2<<<NNODE / 32, 256>>>(msg_fc1_w, msg_fc1_b);

    cudaFuncSetAttribute(k3, cudaFuncAttributeMaxDynamicSharedMemorySize,
                         K3_SMEM);
    k3<<<NBT * 8, 256, K3_SMEM>>>(msg_fc2_w, msg_fc2_b);

    k5<<<NNODE / 16, 256>>>(out_fc1_w, out_fc1_b, out_fc2_w, out_fc2_b,
                            out_fc3_w, out_fc3_b, out);
}